// round 10
// baseline (speedup 1.0000x reference)
#include <cuda_runtime.h>
#include <cuda_fp16.h>
#include <math.h>
#include <stdint.h>

#define NN   100000
#define EE   1600000
#define GG   128
#define DEMB 300
#define DHID 600
#define DIN  20
#define DOUT 64
#define BN_EPS 1e-5f

#define SPLIT_S   0.015625f   // 2^-6
#define SPLIT_INV 64.0f
#define SPLIT_1MS 0.984375f   // 1 - 2^-6

// padded dims
#define KP1   320
#define KP0   64
#define NP1   640
#define KP2   640
#define NP2   384   // GEMM2 N: 300 -> 384 (3 tiles of 128, single launch)
#define HP    320

// ---------------- scratch (device globals) ----------------
__device__ __half g_h[(size_t)NN * HP];     // raw layer output, fp16 (64MB, L2-resident)
__device__ __half g_ah[(size_t)NN * KP1];   // A hi (fp16)
__device__ __half g_ap[(size_t)NN * KP1];   // A P-term
__device__ __half g_th[(size_t)NN * NP1];   // hidden hi / GEMM2 A hi
__device__ __half g_tp[(size_t)NN * NP1];
__device__ __half g_w1h[NP1 * KP1];
__device__ __half g_w1q[NP1 * KP1];
__device__ float  g_b1p[NP1];
__device__ __half g_w2h[NP2 * KP2];
__device__ __half g_w2q[NP2 * KP2];
__device__ float  g_b2p[NP2];

__device__ int   g_rowptr[NN + 1];
__device__ int   g_deg[NN];
__device__ int   g_cursor[NN];
__device__ int   g_csrc[EE];
__device__ float g_esum[NN];
__device__ int   g_blksum[128];
__device__ int   g_blkoff[128];
__device__ float g_colsum[DEMB];
__device__ float g_colsq[DEMB];
__device__ float g_a[DEMB];
__device__ float g_c[DEMB];
__device__ float g_pool[GG * DEMB];
__device__ float g_cnt[GG];

#define SCAN_NB ((NN + 1023) / 1024)

// ---------------- PTX helpers ----------------
__device__ __forceinline__ uint32_t smem_u32(const void* p) {
    uint32_t a;
    asm("{ .reg .u64 t; cvta.to.shared.u64 t, %1; cvt.u32.u64 %0, t; }" : "=r"(a) : "l"(p));
    return a;
}
__device__ __forceinline__ void cp16(uint32_t d, const void* g, bool pred) {
    int sz = pred ? 16 : 0;
    asm volatile("cp.async.cg.shared.global [%0], [%1], 16, %2;"
                 :: "r"(d), "l"(g), "r"(sz) : "memory");
}
#define CP_COMMIT() asm volatile("cp.async.commit_group;" ::: "memory")
#define CP_WAIT1()  asm volatile("cp.async.wait_group 1;" ::: "memory")

__device__ __forceinline__ void ldsm_x4(uint32_t* r, uint32_t a) {
    asm volatile("ldmatrix.sync.aligned.m8n8.x4.shared.b16 {%0,%1,%2,%3}, [%4];"
                 : "=r"(r[0]), "=r"(r[1]), "=r"(r[2]), "=r"(r[3]) : "r"(a));
}
__device__ __forceinline__ void mma_f16(float* c, const uint32_t* a, const uint32_t* b) {
    asm volatile(
        "mma.sync.aligned.m16n8k16.row.col.f32.f16.f16.f32 "
        "{%0,%1,%2,%3}, {%4,%5,%6,%7}, {%8,%9}, {%0,%1,%2,%3};"
        : "+f"(c[0]), "+f"(c[1]), "+f"(c[2]), "+f"(c[3])
        : "r"(a[0]), "r"(a[1]), "r"(a[2]), "r"(a[3]), "r"(b[0]), "r"(b[1]));
}
__device__ __forceinline__ uint32_t swz(uint32_t off) { return off ^ ((off >> 3) & 0x70); }

// producer split: hi = fp16(v), p = fp16((v-hi) + s*hi)
__device__ __forceinline__ void split2(float v, __half& h, __half& p) {
    h = __float2half_rn(v);
    float hf = __half2float(h);
    p = __float2half_rn((v - hf) + SPLIT_S * hf);
}

// ---------------- preprocessing kernels ----------------
__global__ void k_zero_pre() {
    int i = blockIdx.x * blockDim.x + threadIdx.x;
    if (i < NN) { g_deg[i] = 0; g_cursor[i] = 0; g_esum[i] = 0.f; }
}
__global__ void k_zero_pool() {
    int i = blockIdx.x * blockDim.x + threadIdx.x;
    if (i < GG * DEMB) g_pool[i] = 0.f;
    if (i < GG) g_cnt[i] = 0.f;
}
__global__ void k_zero_stats() {
    int i = threadIdx.x;
    if (i < DEMB) { g_colsum[i] = 0.f; g_colsq[i] = 0.f; }
}
__global__ void k_edge_prep(const int* __restrict__ dst, const float* __restrict__ ef) {
    int e = blockIdx.x * blockDim.x + threadIdx.x;
    if (e < EE) {
        int d = dst[e];
        atomicAdd(&g_deg[d], 1);
        atomicAdd(&g_esum[d], ef[e]);
    }
}
__global__ void k_scan1() {
    __shared__ int sh[1024];
    int b = blockIdx.x;
    int i = b * 1024 + threadIdx.x;
    int v = (i < NN) ? g_deg[i] : 0;
    sh[threadIdx.x] = v;
    __syncthreads();
#pragma unroll
    for (int off = 1; off < 1024; off <<= 1) {
        int t = (threadIdx.x >= off) ? sh[threadIdx.x - off] : 0;
        __syncthreads();
        sh[threadIdx.x] += t;
        __syncthreads();
    }
    if (i < NN) g_rowptr[i] = sh[threadIdx.x] - v;
    if (threadIdx.x == 1023) g_blksum[b] = sh[1023];
}
__global__ void k_scan2() {
    __shared__ int sh[128];
    int t = threadIdx.x;
    int v = (t < SCAN_NB) ? g_blksum[t] : 0;
    sh[t] = v;
    __syncthreads();
#pragma unroll
    for (int off = 1; off < 128; off <<= 1) {
        int x = (t >= off) ? sh[t - off] : 0;
        __syncthreads();
        sh[t] += x;
        __syncthreads();
    }
    if (t < SCAN_NB) g_blkoff[t] = sh[t] - v;
    if (t == 0) g_rowptr[NN] = EE;
}
__global__ void k_scan3() {
    int b = blockIdx.x;
    int i = b * 1024 + threadIdx.x;
    if (i < NN) g_rowptr[i] += g_blkoff[b];
}
__global__ void k_edge_fill(const int* __restrict__ src, const int* __restrict__ dst) {
    int e = blockIdx.x * blockDim.x + threadIdx.x;
    if (e < EE) {
        int d = dst[e];
        int pos = atomicAdd(&g_cursor[d], 1);
        g_csrc[g_rowptr[d] + pos] = src[e];
    }
}
__global__ void k_counts(const int* __restrict__ gid) {
    int n = blockIdx.x * blockDim.x + threadIdx.x;
    if (n < NN) atomicAdd(&g_cnt[gid[n]], 1.f);
}

// ---------------- weight prep ----------------
__global__ void k_prepw(const float* __restrict__ w, const float* __restrict__ bias,
                        int K, int Nn, int KPp, int NPp,
                        __half* __restrict__ whT, __half* __restrict__ wqT,
                        float* __restrict__ bp) {
    int idx = blockIdx.x * blockDim.x + threadIdx.x;
    if (idx >= NPp * KPp) return;
    int nrow = idx / KPp, k = idx - nrow * KPp;
    float v = (nrow < Nn && k < K) ? w[(size_t)k * Nn + nrow] : 0.f;
    __half hi = __float2half_rn(v);
    float hf = __half2float(hi);
    whT[idx] = hi;
    wqT[idx] = __float2half_rn(hf + (v - hf) * SPLIT_INV);
    if (k == 0) bp[nrow] = (nrow < Nn) ? bias[nrow] : 0.f;
}

// ---------------- SpMM kernels ----------------
__global__ void k_spmm0(const float* __restrict__ x) {
    int warp = (blockIdx.x * blockDim.x + threadIdx.x) >> 5;
    int lane = threadIdx.x & 31;
    if (warp >= NN) return;
    int beg = g_rowptr[warp], end = g_rowptr[warp + 1];
    float s = 0.f;
    for (int j = beg; j < end; j++) {
        int sn = g_csrc[j];
        if (lane < DIN) s += x[sn * DIN + lane];
    }
    float v0 = (lane < DIN) ? (s + g_esum[warp]) : 0.f;
    size_t o = (size_t)warp * KP0;
    __half h, p;
    split2(v0, h, p);
    g_ah[o + lane] = h;
    g_ap[o + lane] = p;
    g_ah[o + lane + 32] = __float2half_rn(0.f);
    g_ap[o + lane + 32] = __float2half_rn(0.f);
}

// h stored fp16 (half2 reads); BN folded; edge loop unrolled x2 for MLP
__global__ void k_spmm300() {
    int n = blockIdx.x;
    int t = threadIdx.x;  // 128
    int beg = g_rowptr[n], end = g_rowptr[n + 1];
    float sx = 0.f, sy = 0.f, ux = 0.f, uy = 0.f;
    const __half2* hbase = (const __half2*)g_h;
    int j = beg;
    for (; j + 1 < end; j += 2) {
        const __half2* r0 = hbase + (size_t)g_csrc[j] * (HP / 2);
        const __half2* r1 = hbase + (size_t)g_csrc[j + 1] * (HP / 2);
        float2 a0 = __half22float2(r0[t]);
        float2 a1 = __half22float2(r1[t]);
        float2 b0 = __half22float2(r0[t + 128]);
        float2 b1 = __half22float2(r1[t + 128]);
        sx += a0.x + a1.x; sy += a0.y + a1.y;
        if (t < 32) { ux += b0.x + b1.x; uy += b0.y + b1.y; }
    }
    if (j < end) {
        const __half2* r0 = hbase + (size_t)g_csrc[j] * (HP / 2);
        float2 a0 = __half22float2(r0[t]);
        sx += a0.x; sy += a0.y;
        if (t < 32) {
            float2 b0 = __half22float2(r0[t + 128]);
            ux += b0.x; uy += b0.y;
        }
    }
    float es = g_esum[n];
    float dg = (float)(end - beg);
    size_t o = (size_t)n * KP1;
    int f = 2 * t;
    float v0 = g_a[f] * sx + dg * g_c[f] + es;
    float v1 = g_a[f + 1] * sy + dg * g_c[f + 1] + es;
    __half h0, p0, h1, p1;
    split2(v0, h0, p0);
    split2(v1, h1, p1);
    *(__half2*)(g_ah + o + f) = __halves2half2(h0, h1);
    *(__half2*)(g_ap + o + f) = __halves2half2(p0, p1);
    if (t < 32) {
        int f2 = 256 + 2 * t;
        float v2 = (f2 < DEMB)     ? (g_a[f2] * ux + dg * g_c[f2] + es) : 0.f;
        float v3 = (f2 + 1 < DEMB) ? (g_a[f2 + 1] * uy + dg * g_c[f2 + 1] + es) : 0.f;
        __half h2, p2, h3, p3;
        split2(v2, h2, p2);
        split2(v3, h3, p3);
        *(__half2*)(g_ah + o + f2) = __halves2half2(h2, h3);
        *(__half2*)(g_ap + o + f2) = __halves2half2(p2, p3);
    }
}

// ---------------- fp16 2-MMA compensated GEMM, 256 threads / 8 warps ----------------
// Warp tile 64x32 (2m x 4n, MI=4). Grid: (n-tiles, m-tiles) n-fast.
// MODE 0: bias + ReLU -> Oh/Op fp16 (pitch NP1)
// MODE 1: bias -> H fp16 (pitch HP, cols<HP) + column stats (cols<DEMB)
#define BM 128
#define BK 64
#define GTHREADS 256
#define NWARPS 8
#define BNT 128

template <int MODE>
__global__ __launch_bounds__(GTHREADS, 1) void k_gemm(
    const __half* __restrict__ Ah, const __half* __restrict__ Ap, int KP,
    const __half* __restrict__ Bh, const __half* __restrict__ Bq,
    const float* __restrict__ biasp, int nk,
    __half* __restrict__ Oh, __half* __restrict__ Op,
    __half* __restrict__ H, float* __restrict__ colsum, float* __restrict__ colsq) {
    constexpr int WN_W = BNT / 32;            // 4
    constexpr int WM_W = NWARPS / WN_W;       // 2
    constexpr int MT_W = BM / WM_W;           // 64
    constexpr int MI   = MT_W / 16;           // 4
    constexpr int OFF_AP_ = 16384;
    constexpr int OFF_BH_ = 32768;
    constexpr int OFF_BQ_ = 32768 + BNT * 128;
    constexpr int STAGE_  = 32768 + 2 * BNT * 128;

    extern __shared__ char dyn[];
    __shared__ float s_bias[BNT];
    __shared__ float s_sum[BNT], s_sq[BNT];

    int tid = threadIdx.x;
    int wid = tid >> 5;
    int lane = tid & 31;
    int wm = wid / WN_W;
    int wn = wid % WN_W;
    int m0 = blockIdx.y * BM;                  // m on y (slow)
    int n0 = blockIdx.x * BNT;                 // n on x (fast)

    uint32_t dynb0 = smem_u32(dyn);
    uint32_t dynb = (dynb0 + 1023u) & ~1023u;

    if (tid < BNT) {
        s_bias[tid] = biasp[n0 + tid];
        if (MODE == 1) { s_sum[tid] = 0.f; s_sq[tid] = 0.f; }
    }

    float acc1[MI][4][4] = {};
    float acc2[MI][4][4] = {};

    auto load_stage = [&](int s, int kt) {
        uint32_t ab = dynb + s * STAGE_;
        int k0 = kt * BK;
#pragma unroll
        for (int it = 0; it < 2048 / GTHREADS; it++) {
            int i = tid + it * GTHREADS;
            int var = i >> 10;
            int j = i & 1023;
            int r = j >> 3, sg = j & 7;
            const __half* base = var ? Ap : Ah;
            const void* g = base + (size_t)(m0 + r) * KP + k0 + sg * 8;
            uint32_t d = ab + (var ? OFF_AP_ : 0) + swz((uint32_t)(r * 128 + sg * 16));
            cp16(d, g, (m0 + r) < NN);
        }
#pragma unroll
        for (int it = 0; it < BNT * 16 / GTHREADS; it++) {
            int i = tid + it * GTHREADS;
            int var = i / (BNT * 8);
            int j = i % (BNT * 8);
            int r = j >> 3, sg = j & 7;
            const __half* base = var ? Bq : Bh;
            const void* g = base + (size_t)(n0 + r) * KP + k0 + sg * 8;
            uint32_t d = ab + (var ? OFF_BQ_ : OFF_BH_) + swz((uint32_t)(r * 128 + sg * 16));
            cp16(d, g, true);
        }
    };

    int lr = lane & 15;
    int lc = ((lane >> 4) & 1) * 16;

    auto compute = [&](int s) {
        uint32_t ab = dynb + s * STAGE_;
#pragma unroll
        for (int ks = 0; ks < 4; ks++) {
            int kb = ks * 32;
            uint32_t ah[MI][4], ap[MI][4];
#pragma unroll
            for (int mi = 0; mi < MI; mi++) {
                uint32_t off = swz((uint32_t)((wm * MT_W + mi * 16 + lr) * 128 + kb + lc));
                ldsm_x4(ah[mi], ab + off);
                ldsm_x4(ap[mi], ab + OFF_AP_ + off);
            }
            uint32_t bh[2][4], bq[2][4];
#pragma unroll
            for (int bi = 0; bi < 2; bi++) {
                uint32_t off = swz((uint32_t)((wn * 32 + bi * 16 + lr) * 128 + kb + lc));
                ldsm_x4(bh[bi], ab + OFF_BH_ + off);
                ldsm_x4(bq[bi], ab + OFF_BQ_ + off);
            }
#pragma unroll
            for (int mi = 0; mi < MI; mi++) {
#pragma unroll
                for (int t = 0; t < 4; t++) {
                    uint32_t bfh[2] = { bh[t >> 1][t & 1], bh[t >> 1][(t & 1) + 2] };
                    uint32_t bfq[2] = { bq[t >> 1][t & 1], bq[t >> 1][(t & 1) + 2] };
                    mma_f16(acc1[mi][t], ah[mi], bfh);
                    mma_f16(acc2[mi][t], ap[mi], bfq);
                }
            }
        }
    };

    load_stage(0, 0);
    CP_COMMIT();
    if (nk > 1) load_stage(1, 1);
    CP_COMMIT();
    for (int kt = 0; kt < nk; kt++) {
        CP_WAIT1();
        __syncthreads();
        if (kt + 2 < nk) load_stage((kt + 2) % 3, kt + 2);
        CP_COMMIT();
        compute(kt % 3);
    }

    // ---------------- epilogue ----------------
    int lrow = lane >> 2;
    int lcol = (lane & 3) * 2;

    if (MODE == 0) {
#pragma unroll
        for (int mi = 0; mi < MI; mi++) {
            int gm = m0 + wm * MT_W + mi * 16 + lrow;
#pragma unroll
            for (int t = 0; t < 4; t++) {
                int c = wn * 32 + t * 8 + lcol;
                float b0 = s_bias[c], b1 = s_bias[c + 1];
                int cg = n0 + c;
#pragma unroll
                for (int rr = 0; rr < 2; rr++) {
                    int g = gm + rr * 8;
                    if (g < NN) {
                        float v0 = fmaxf(SPLIT_1MS * acc1[mi][t][rr * 2 + 0] +
                                         acc2[mi][t][rr * 2 + 0] + b0, 0.f);
                        float v1 = fmaxf(SPLIT_1MS * acc1[mi][t][rr * 2 + 1] +
                                         acc2[mi][t][rr * 2 + 1] + b1, 0.f);
                        __half h0, p0, h1, p1;
                        split2(v0, h0, p0);
                        split2(v1, h1, p1);
                        uint32_t hp = (uint32_t)__half_as_ushort(h0) |
                                      ((uint32_t)__half_as_ushort(h1) << 16);
                        uint32_t pp = (uint32_t)__half_as_ushort(p0) |
                                      ((uint32_t)__half_as_ushort(p1) << 16);
                        *(uint32_t*)(Oh + (size_t)g * NP1 + cg) = hp;
                        *(uint32_t*)(Op + (size_t)g * NP1 + cg) = pp;
                    }
                }
            }
        }
    } else {
#pragma unroll
        for (int t = 0; t < 4; t++) {
            int c = wn * 32 + t * 8 + lcol;
            int cg = n0 + c;
            float b0 = s_bias[c], b1 = s_bias[c + 1];
            float s0 = 0.f, s1 = 0.f, q0 = 0.f, q1 = 0.f;
#pragma unroll
            for (int mi = 0; mi < MI; mi++) {
                int gm = m0 + wm * MT_W + mi * 16 + lrow;
                float v0 = SPLIT_1MS * acc1[mi][t][0] + acc2[mi][t][0] + b0;
                float v1 = SPLIT_1MS * acc1[mi][t][1] + acc2[mi][t][1] + b1;
                float v2 = SPLIT_1MS * acc1[mi][t][2] + acc2[mi][t][2] + b0;
                float v3 = SPLIT_1MS * acc1[mi][t][3] + acc2[mi][t][3] + b1;
                if (gm >= NN) { v0 = 0.f; v1 = 0.f; }
                if (gm + 8 >= NN) { v2 = 0.f; v3 = 0.f; }
                if (cg < HP) {
                    if (gm < NN)
                        *(__half2*)(H + (size_t)gm * HP + cg) = __floats2half2_rn(v0, v1);
                    if (gm + 8 < NN)
                        *(__half2*)(H + (size_t)(gm + 8) * HP + cg) = __floats2half2_rn(v2, v3);
                }
                s0 += v0 + v2; s1 += v1 + v3;
                q0 += v0 * v0 + v2 * v2; q1 += v1 * v1 + v3 * v3;
            }
#pragma unroll
            for (int off = 4; off < 32; off <<= 1) {
                s0 += __shfl_xor_sync(0xffffffffu, s0, off);
                s1 += __shfl_xor_sync(0xffffffffu, s1, off);
                q0 += __shfl_xor_sync(0xffffffffu, q0, off);
                q1 += __shfl_xor_sync(0xffffffffu, q1, off);
            }
            if (lane < 4) {
                if (cg < DEMB) { atomicAdd(&s_sum[c], s0); atomicAdd(&s_sq[c], q0); }
                if (cg + 1 < DEMB) { atomicAdd(&s_sum[c + 1], s1); atomicAdd(&s_sq[c + 1], q1); }
            }
        }
        __syncthreads();
        if (tid < BNT) {
            int n = n0 + tid;
            if (n < DEMB) {
                atomicAdd(&colsum[n], s_sum[tid]);
                atomicAdd(&colsq[n], s_sq[tid]);
            }
        }
    }
}

// ---------------- BN finalize ----------------
__global__ void k_bnfin(const float* __restrict__ gamma, const float* __restrict__ beta) {
    int f = threadIdx.x;
    if (f >= DEMB) return;
    const float invM = 1.0f / (float)NN;
    float mu = g_colsum[f] * invM;
    float var = g_colsq[f] * invM - mu * mu;
    float a = gamma[f] * rsqrtf(var + BN_EPS);
    g_a[f] = a;
    g_c[f] = beta[f] - mu * a;
}

// ---------------- pooling (reads fp16 h) ----------------
#define POOL_TILE 32
__global__ void k_pool(const int* __restrict__ gid) {
    int f = blockIdx.y * 128 + threadIdx.x;
    if (f >= DEMB) return;
    int n0 = blockIdx.x * POOL_TILE;
    float acc = 0.f;
    int cur = gid[n0];
    for (int i = 0; i < POOL_TILE; i++) {
        int n = n0 + i;
        int g = gid[n];
        if (g != cur) {
            atomicAdd(&g_pool[cur * DEMB + f], acc);
            acc = 0.f;
            cur = g;
        }
        acc += __half2float(g_h[(size_t)n * HP + f]);
    }
    atomicAdd(&g_pool[cur * DEMB + f], acc);
}

// ---------------- final ----------------
__global__ void k_final(const float* __restrict__ wt, const float* __restrict__ bt,
                        float* __restrict__ out) {
    int g = blockIdx.x;
    int o = threadIdx.x;
    float cnt = g_cnt[g];
    float inv = 1.0f / fmaxf(cnt, 1.f);
    float acc = 0.f;
    for (int f = 0; f < DEMB; f++) {
        float pf = (g_a[f] * g_pool[g * DEMB + f] + cnt * g_c[f]) * inv;
        acc += pf * wt[f * DOUT + o];
    }
    out[g * DOUT + o] = acc + bt[o];
}

// ---------------- host launcher ----------------
#define GSMEM (3 * (32768 + 2 * 128 * 128) + 1024)

extern "C" void kernel_launch(void* const* d_in, const int* in_sizes, int n_in,
                              void* d_out, int out_size) {
    const float* node_feats = (const float*)d_in[0];
    const float* edge_feats = (const float*)d_in[1];
    const int*   src        = (const int*)d_in[2];
    const int*   dst        = (const int*)d_in[3];
    const int*   gid        = (const int*)d_in[4];
    const float* w1_0  = (const float*)d_in[5];
    const float* b1_0  = (const float*)d_in[6];
    const float* w2_0  = (const float*)d_in[7];
    const float* b2_0  = (const float*)d_in[8];
    const float* gamma0 = (const float*)d_in[9];
    const float* beta0  = (const float*)d_in[10];
    const float* w1   = (const float*)d_in[11];
    const float* b1   = (const float*)d_in[12];
    const float* w2   = (const float*)d_in[13];
    const float* b2   = (const float*)d_in[14];
    const float* gamma = (const float*)d_in[15];
    const float* beta  = (const float*)d_in[16];
    const float* wt   = (const float*)d_in[17];
    const float* bt   = (const float*)d_in[18];
    float* out = (float*)d_out;

    static bool attr_done = false;
    if (!attr_done) {
        cudaFuncSetAttribute(k_gemm<0>, cudaFuncAttributeMaxDynamicSharedMemorySize, GSMEM);
        cudaFuncSetAttribute(k_gemm<1>, cudaFuncAttributeMaxDynamicSharedMemorySize, GSMEM);
        attr_done = true;
    }

    __half *p_ah, *p_ap, *p_th, *p_tp, *p_w1h, *p_w1q, *p_w2h, *p_w2q, *p_h;
    float *p_b1p, *p_b2p, *p_colsum, *p_colsq;
    cudaGetSymbolAddress((void**)&p_ah, g_ah);
    cudaGetSymbolAddress((void**)&p_ap, g_ap);
    cudaGetSymbolAddress((void**)&p_th, g_th);
    cudaGetSymbolAddress((void**)&p_tp, g_tp);
    cudaGetSymbolAddress((void**)&p_w1h, g_w1h);
    cudaGetSymbolAddress((void**)&p_w1q, g_w1q);
    cudaGetSymbolAddress((void**)&p_w2h, g_w2h);
    cudaGetSymbolAddress((void**)&p_w2q, g_w2q);
    cudaGetSymbolAddress((void**)&p_h, g_h);
    cudaGetSymbolAddress((void**)&p_b1p, g_b1p);
    cudaGetSymbolAddress((void**)&p_b2p, g_b2p);
    cudaGetSymbolAddress((void**)&p_colsum, g_colsum);
    cudaGetSymbolAddress((void**)&p_colsq, g_colsq);

    // ---- preprocessing ----
    k_prepw<<<(NP1 * KP0 + 255) / 256, 256>>>(w1_0, b1_0, DIN, DHID, KP0, NP1,
                                              p_w1h, p_w1q, p_b1p);
    k_prepw<<<(NP2 * KP2 + 255) / 256, 256>>>(w2_0, b2_0, DHID, DEMB, KP2, NP2,
                                              p_w2h, p_w2q, p_b2p);
    k_zero_pre<<<(NN + 255) / 256, 256>>>();
    k_zero_pool<<<(GG * DEMB + 255) / 256, 256>>>();
    k_edge_prep<<<(EE + 255) / 256, 256>>>(dst, edge_feats);
    k_scan1<<<SCAN_NB, 1024>>>();
    k_scan2<<<1, 128>>>();
    k_scan3<<<SCAN_NB, 1024>>>();
    k_edge_fill<<<(EE + 255) / 256, 256>>>(src, dst);
    k_counts<<<(NN + 255) / 256, 256>>>(gid);

    const int MT = (NN + BM - 1) / BM;
    dim3 grid1(NP1 / BNT, MT);    // (5, 782) n-fast
    dim3 grid2(NP2 / BNT, MT);    // (3, 782) n-fast, single launch

    // ---- layer 0 ----
    k_spmm0<<<(NN * 32 + 255) / 256, 256>>>(node_feats);
    k_zero_stats<<<1, 320>>>();
    k_gemm<0><<<grid1, GTHREADS, GSMEM>>>(p_ah, p_ap, KP0, p_w1h, p_w1q, p_b1p,
                                          KP0 / BK, p_th, p_tp, nullptr, nullptr, nullptr);
    k_gemm<1><<<grid2, GTHREADS, GSMEM>>>(p_th, p_tp, KP2, p_w2h, p_w2q, p_b2p,
                                          KP2 / BK, nullptr, nullptr, p_h, p_colsum, p_colsq);
    k_bnfin<<<1, 320>>>(gamma0, beta0);

    // ---- layers 1..4 ----
    for (int l = 0; l < 4; l++) {
        k_prepw<<<(NP1 * KP1 + 255) / 256, 256>>>(w1 + (size_t)l * DEMB * DHID,
                                                  b1 + (size_t)l * DHID, DEMB, DHID, KP1, NP1,
                                                  p_w1h, p_w1q, p_b1p);
        k_prepw<<<(NP2 * KP2 + 255) / 256, 256>>>(w2 + (size_t)l * DHID * DEMB,
                                                  b2 + (size_t)l * DEMB, DHID, DEMB, KP2, NP2,
                                                  p_w2h, p_w2q, p_b2p);
        k_spmm300<<<NN, 128>>>();
        k_zero_stats<<<1, 320>>>();
        k_gemm<0><<<grid1, GTHREADS, GSMEM>>>(p_ah, p_ap, KP1, p_w1h, p_w1q, p_b1p,
                                              KP1 / BK, p_th, p_tp, nullptr, nullptr, nullptr);
        k_gemm<1><<<grid2, GTHREADS, GSMEM>>>(p_th, p_tp, KP2, p_w2h, p_w2q, p_b2p,
                                              KP2 / BK, nullptr, nullptr, p_h, p_colsum, p_colsq);
        k_bnfin<<<1, 320>>>(gamma + (size_t)l * DEMB, beta + (size_t)l * DEMB);
    }

    // ---- readout ----
    k_pool<<<dim3(NN / POOL_TILE, (DEMB + 127) / 128), 128>>>(gid);
    k_final<<<GG, DOUT>>>(wt, bt, out);
}

// round 17
// speedup vs baseline: 1.0228x; 1.0228x over previous
#include <cuda_runtime.h>
#include <cuda_fp16.h>
#include <math.h>
#include <stdint.h>

#define NN   100000
#define EE   1600000
#define GG   128
#define DEMB 300
#define DHID 600
#define DIN  20
#define DOUT 64
#define BN_EPS 1e-5f

#define SPLIT_S   0.015625f   // 2^-6
#define SPLIT_INV 64.0f
#define SPLIT_1MS 0.984375f   // 1 - 2^-6

// padded dims
#define KP1   320
#define KP0   64
#define NP1   640
#define KP2   640
#define NP2   320
#define HP    320

// ---------------- scratch (device globals) ----------------
__device__ __half g_h[(size_t)NN * HP];     // raw layer output, fp16 (64MB, L2-resident)
__device__ __half g_ah[(size_t)NN * KP1];   // A hi (fp16)
__device__ __half g_ap[(size_t)NN * KP1];   // A P-term
__device__ __half g_th[(size_t)NN * NP1];   // hidden hi / GEMM2 A hi
__device__ __half g_tp[(size_t)NN * NP1];
__device__ __half g_w1h[NP1 * KP1];
__device__ __half g_w1q[NP1 * KP1];
__device__ float  g_b1p[NP1];
__device__ __half g_w2h[NP2 * KP2];
__device__ __half g_w2q[NP2 * KP2];
__device__ float  g_b2p[NP2];

__device__ int   g_rowptr[NN + 1];
__device__ int   g_deg[NN];
__device__ int   g_cursor[NN];
__device__ int   g_csrc[EE];
__device__ float g_esum[NN];
__device__ int   g_blksum[128];
__device__ int   g_blkoff[128];
__device__ float g_colsum[DEMB];
__device__ float g_colsq[DEMB];
__device__ float g_a[DEMB];
__device__ float g_c[DEMB];
__device__ float g_pool[GG * DEMB];
__device__ float g_cnt[GG];

#define SCAN_NB ((NN + 1023) / 1024)

// ---------------- PTX helpers ----------------
__device__ __forceinline__ uint32_t smem_u32(const void* p) {
    uint32_t a;
    asm("{ .reg .u64 t; cvta.to.shared.u64 t, %1; cvt.u32.u64 %0, t; }" : "=r"(a) : "l"(p));
    return a;
}
__device__ __forceinline__ void cp16(uint32_t d, const void* g, bool pred) {
    int sz = pred ? 16 : 0;
    asm volatile("cp.async.cg.shared.global [%0], [%1], 16, %2;"
                 :: "r"(d), "l"(g), "r"(sz) : "memory");
}
#define CP_COMMIT() asm volatile("cp.async.commit_group;" ::: "memory")
#define CP_WAIT1()  asm volatile("cp.async.wait_group 1;" ::: "memory")

__device__ __forceinline__ void ldsm_x4(uint32_t* r, uint32_t a) {
    asm volatile("ldmatrix.sync.aligned.m8n8.x4.shared.b16 {%0,%1,%2,%3}, [%4];"
                 : "=r"(r[0]), "=r"(r[1]), "=r"(r[2]), "=r"(r[3]) : "r"(a));
}
__device__ __forceinline__ void mma_f16(float* c, const uint32_t* a, const uint32_t* b) {
    asm volatile(
        "mma.sync.aligned.m16n8k16.row.col.f32.f16.f16.f32 "
        "{%0,%1,%2,%3}, {%4,%5,%6,%7}, {%8,%9}, {%0,%1,%2,%3};"
        : "+f"(c[0]), "+f"(c[1]), "+f"(c[2]), "+f"(c[3])
        : "r"(a[0]), "r"(a[1]), "r"(a[2]), "r"(a[3]), "r"(b[0]), "r"(b[1]));
}
__device__ __forceinline__ uint32_t swz(uint32_t off) { return off ^ ((off >> 3) & 0x70); }

// producer split: hi = fp16(v), p = fp16((v-hi) + s*hi)
__device__ __forceinline__ void split2(float v, __half& h, __half& p) {
    h = __float2half_rn(v);
    float hf = __half2float(h);
    p = __float2half_rn((v - hf) + SPLIT_S * hf);
}

// ---------------- preprocessing kernels ----------------
__global__ void k_zero_pre() {
    int i = blockIdx.x * blockDim.x + threadIdx.x;
    if (i < NN) { g_deg[i] = 0; g_cursor[i] = 0; g_esum[i] = 0.f; }
}
__global__ void k_zero_pool() {
    int i = blockIdx.x * blockDim.x + threadIdx.x;
    if (i < GG * DEMB) g_pool[i] = 0.f;
    if (i < GG) g_cnt[i] = 0.f;
}
__global__ void k_zero_stats() {
    int i = threadIdx.x;
    if (i < DEMB) { g_colsum[i] = 0.f; g_colsq[i] = 0.f; }
}
__global__ void k_edge_prep(const int* __restrict__ dst, const float* __restrict__ ef) {
    int e = blockIdx.x * blockDim.x + threadIdx.x;
    if (e < EE) {
        int d = dst[e];
        atomicAdd(&g_deg[d], 1);
        atomicAdd(&g_esum[d], ef[e]);
    }
}
__global__ void k_scan1() {
    __shared__ int sh[1024];
    int b = blockIdx.x;
    int i = b * 1024 + threadIdx.x;
    int v = (i < NN) ? g_deg[i] : 0;
    sh[threadIdx.x] = v;
    __syncthreads();
#pragma unroll
    for (int off = 1; off < 1024; off <<= 1) {
        int t = (threadIdx.x >= off) ? sh[threadIdx.x - off] : 0;
        __syncthreads();
        sh[threadIdx.x] += t;
        __syncthreads();
    }
    if (i < NN) g_rowptr[i] = sh[threadIdx.x] - v;
    if (threadIdx.x == 1023) g_blksum[b] = sh[1023];
}
__global__ void k_scan2() {
    __shared__ int sh[128];
    int t = threadIdx.x;
    int v = (t < SCAN_NB) ? g_blksum[t] : 0;
    sh[t] = v;
    __syncthreads();
#pragma unroll
    for (int off = 1; off < 128; off <<= 1) {
        int x = (t >= off) ? sh[t - off] : 0;
        __syncthreads();
        sh[t] += x;
        __syncthreads();
    }
    if (t < SCAN_NB) g_blkoff[t] = sh[t] - v;
    if (t == 0) g_rowptr[NN] = EE;
}
__global__ void k_scan3() {
    int b = blockIdx.x;
    int i = b * 1024 + threadIdx.x;
    if (i < NN) g_rowptr[i] += g_blkoff[b];
}
__global__ void k_edge_fill(const int* __restrict__ src, const int* __restrict__ dst) {
    int e = blockIdx.x * blockDim.x + threadIdx.x;
    if (e < EE) {
        int d = dst[e];
        int pos = atomicAdd(&g_cursor[d], 1);
        g_csrc[g_rowptr[d] + pos] = src[e];
    }
}
__global__ void k_counts(const int* __restrict__ gid) {
    int n = blockIdx.x * blockDim.x + threadIdx.x;
    if (n < NN) atomicAdd(&g_cnt[gid[n]], 1.f);
}

// ---------------- weight prep ----------------
__global__ void k_prepw(const float* __restrict__ w, const float* __restrict__ bias,
                        int K, int Nn, int KPp, int NPp,
                        __half* __restrict__ whT, __half* __restrict__ wqT,
                        float* __restrict__ bp) {
    int idx = blockIdx.x * blockDim.x + threadIdx.x;
    if (idx >= NPp * KPp) return;
    int nrow = idx / KPp, k = idx - nrow * KPp;
    float v = (nrow < Nn && k < K) ? w[(size_t)k * Nn + nrow] : 0.f;
    __half hi = __float2half_rn(v);
    float hf = __half2float(hi);
    whT[idx] = hi;
    wqT[idx] = __float2half_rn(hf + (v - hf) * SPLIT_INV);
    if (k == 0) bp[nrow] = (nrow < Nn) ? bias[nrow] : 0.f;
}

// ---------------- SpMM kernels ----------------
__global__ void k_spmm0(const float* __restrict__ x) {
    int warp = (blockIdx.x * blockDim.x + threadIdx.x) >> 5;
    int lane = threadIdx.x & 31;
    if (warp >= NN) return;
    int beg = g_rowptr[warp], end = g_rowptr[warp + 1];
    float s = 0.f;
    for (int j = beg; j < end; j++) {
        int sn = g_csrc[j];
        if (lane < DIN) s += x[sn * DIN + lane];
    }
    float v0 = (lane < DIN) ? (s + g_esum[warp]) : 0.f;
    size_t o = (size_t)warp * KP0;
    __half h, p;
    split2(v0, h, p);
    g_ah[o + lane] = h;
    g_ap[o + lane] = p;
    g_ah[o + lane + 32] = __float2half_rn(0.f);
    g_ap[o + lane + 32] = __float2half_rn(0.f);
}

// h stored fp16 (half2 reads); BN folded; edge loop unrolled x2 for MLP
__global__ void k_spmm300() {
    int n = blockIdx.x;
    int t = threadIdx.x;  // 128
    int beg = g_rowptr[n], end = g_rowptr[n + 1];
    float sx = 0.f, sy = 0.f, ux = 0.f, uy = 0.f;
    const __half2* hbase = (const __half2*)g_h;
    int j = beg;
    for (; j + 1 < end; j += 2) {
        const __half2* r0 = hbase + (size_t)g_csrc[j] * (HP / 2);
        const __half2* r1 = hbase + (size_t)g_csrc[j + 1] * (HP / 2);
        float2 a0 = __half22float2(r0[t]);
        float2 a1 = __half22float2(r1[t]);
        float2 b0 = __half22float2(r0[t + 128]);
        float2 b1 = __half22float2(r1[t + 128]);
        sx += a0.x + a1.x; sy += a0.y + a1.y;
        if (t < 32) { ux += b0.x + b1.x; uy += b0.y + b1.y; }
    }
    if (j < end) {
        const __half2* r0 = hbase + (size_t)g_csrc[j] * (HP / 2);
        float2 a0 = __half22float2(r0[t]);
        sx += a0.x; sy += a0.y;
        if (t < 32) {
            float2 b0 = __half22float2(r0[t + 128]);
            ux += b0.x; uy += b0.y;
        }
    }
    float es = g_esum[n];
    float dg = (float)(end - beg);
    size_t o = (size_t)n * KP1;
    int f = 2 * t;
    float v0 = g_a[f] * sx + dg * g_c[f] + es;
    float v1 = g_a[f + 1] * sy + dg * g_c[f + 1] + es;
    __half h0, p0, h1, p1;
    split2(v0, h0, p0);
    split2(v1, h1, p1);
    *(__half2*)(g_ah + o + f) = __halves2half2(h0, h1);
    *(__half2*)(g_ap + o + f) = __halves2half2(p0, p1);
    if (t < 32) {
        int f2 = 256 + 2 * t;
        float v2 = (f2 < DEMB)     ? (g_a[f2] * ux + dg * g_c[f2] + es) : 0.f;
        float v3 = (f2 + 1 < DEMB) ? (g_a[f2 + 1] * uy + dg * g_c[f2 + 1] + es) : 0.f;
        __half h2, p2, h3, p3;
        split2(v2, h2, p2);
        split2(v3, h3, p3);
        *(__half2*)(g_ah + o + f2) = __halves2half2(h2, h3);
        *(__half2*)(g_ap + o + f2) = __halves2half2(p2, p3);
    }
}

// ---------------- fp16 2-MMA compensated GEMM, 256 threads / 8 warps ----------------
// Warp tile 64x32 (BNT=128: 2m x 4n, MI=4). Grid: (n-tiles, m-tiles) n-fast.
// MODE 0: bias + ReLU -> Oh/Op fp16 (pitch NP1)
// MODE 1: bias -> H fp16 (pitch HP, cols<HP) + column stats (cols<DEMB)
#define BM 128
#define BK 64
#define GTHREADS 256
#define NWARPS 8

template <int MODE, int BNT>
__global__ __launch_bounds__(GTHREADS, 1) void k_gemm(
    const __half* __restrict__ Ah, const __half* __restrict__ Ap, int KP,
    const __half* __restrict__ Bh, const __half* __restrict__ Bq,
    const float* __restrict__ biasp, int nk, int n0_base,
    __half* __restrict__ Oh, __half* __restrict__ Op,
    __half* __restrict__ H, float* __restrict__ colsum, float* __restrict__ colsq) {
    constexpr int WN_W = BNT / 32;            // warps along n (4 or 2)
    constexpr int WM_W = NWARPS / WN_W;       // warps along m (2 or 4)
    constexpr int MT_W = BM / WM_W;           // rows per warp (64 or 32)
    constexpr int MI   = MT_W / 16;           // 16-row chunks (4 or 2)
    constexpr int OFF_AP_ = 16384;
    constexpr int OFF_BH_ = 32768;
    constexpr int OFF_BQ_ = 32768 + BNT * 128;
    constexpr int STAGE_  = 32768 + 2 * BNT * 128;

    extern __shared__ char dyn[];
    __shared__ float s_bias[128];
    __shared__ float s_sum[128], s_sq[128];

    int tid = threadIdx.x;
    int wid = tid >> 5;
    int lane = tid & 31;
    int wm = wid / WN_W;
    int wn = wid % WN_W;
    int m0 = blockIdx.y * BM;                  // m on y (slow)
    int n0 = n0_base + blockIdx.x * BNT;       // n on x (fast)

    uint32_t dynb0 = smem_u32(dyn);
    uint32_t dynb = (dynb0 + 1023u) & ~1023u;

    if (tid < BNT) {
        s_bias[tid] = biasp[n0 + tid];
        if (MODE == 1) { s_sum[tid] = 0.f; s_sq[tid] = 0.f; }
    }

    float acc1[MI][4][4] = {};
    float acc2[MI][4][4] = {};

    auto load_stage = [&](int s, int kt) {
        uint32_t ab = dynb + s * STAGE_;
        int k0 = kt * BK;
#pragma unroll
        for (int it = 0; it < 2048 / GTHREADS; it++) {   // A hi+lo: 2048 cp16
            int i = tid + it * GTHREADS;
            int var = i >> 10;
            int j = i & 1023;
            int r = j >> 3, sg = j & 7;
            const __half* base = var ? Ap : Ah;
            const void* g = base + (size_t)(m0 + r) * KP + k0 + sg * 8;
            uint32_t d = ab + (var ? OFF_AP_ : 0) + swz((uint32_t)(r * 128 + sg * 16));
            cp16(d, g, (m0 + r) < NN);
        }
#pragma unroll
        for (int it = 0; it < BNT * 16 / GTHREADS; it++) {   // B hi+lo
            int i = tid + it * GTHREADS;
            int var = i / (BNT * 8);
            int j = i % (BNT * 8);
            int r = j >> 3, sg = j & 7;
            const __half* base = var ? Bq : Bh;
            const void* g = base + (size_t)(n0 + r) * KP + k0 + sg * 8;
            uint32_t d = ab + (var ? OFF_BQ_ : OFF_BH_) + swz((uint32_t)(r * 128 + sg * 16));
            cp16(d, g, true);
        }
    };

    int lr = lane & 15;
    int lc = ((lane >> 4) & 1) * 16;

    auto compute = [&](int s) {
        uint32_t ab = dynb + s * STAGE_;
#pragma unroll
        for (int ks = 0; ks < 4; ks++) {
            int kb = ks * 32;
            uint32_t ah[MI][4], ap[MI][4];
#pragma unroll
            for (int mi = 0; mi < MI; mi++) {
                uint32_t off = swz((uint32_t)((wm * MT_W + mi * 16 + lr) * 128 + kb + lc));
                ldsm_x4(ah[mi], ab + off);
                ldsm_x4(ap[mi], ab + OFF_AP_ + off);
            }
            uint32_t bh[2][4], bq[2][4];
#pragma unroll
            for (int bi = 0; bi < 2; bi++) {
                uint32_t off = swz((uint32_t)((wn * 32 + bi * 16 + lr) * 128 + kb + lc));
                ldsm_x4(bh[bi], ab + OFF_BH_ + off);
                ldsm_x4(bq[bi], ab + OFF_BQ_ + off);
            }
#pragma unroll
            for (int mi = 0; mi < MI; mi++) {
#pragma unroll
                for (int t = 0; t < 4; t++) {
                    uint32_t bfh[2] = { bh[t >> 1][t & 1], bh[t >> 1][(t & 1) + 2] };
                    uint32_t bfq[2] = { bq[t >> 1][t & 1], bq[t >> 1][(t & 1) + 2] };
                    mma_f16(acc1[mi][t], ah[mi], bfh);
                    mma_f16(acc2[mi][t], ap[mi], bfq);
                }
            }
        }
    };

    load_stage(0, 0);
    CP_COMMIT();
    if (nk > 1) load_stage(1, 1);
    CP_COMMIT();
    for (int kt = 0; kt < nk; kt++) {
        CP_WAIT1();
        __syncthreads();
        if (kt + 2 < nk) load_stage((kt + 2) % 3, kt + 2);
        CP_COMMIT();
        compute(kt % 3);
    }

    // ---------------- epilogue ----------------
    int lrow = lane >> 2;
    int lcol = (lane & 3) * 2;

    if (MODE == 0) {
#pragma unroll
        for (int mi = 0; mi < MI; mi++) {
            int gm = m0 + wm * MT_W + mi * 16 + lrow;
#pragma unroll
            for (int t = 0; t < 4; t++) {
                int c = wn * 32 + t * 8 + lcol;
                float b0 = s_bias[c], b1 = s_bias[c + 1];
                int cg = n0 + c;
#pragma unroll
                for (int rr = 0; rr < 2; rr++) {
                    int g = gm + rr * 8;
                    if (g < NN) {
                        float v0 = fmaxf(SPLIT_1MS * acc1[mi][t][rr * 2 + 0] +
                                         acc2[mi][t][rr * 2 + 0] + b0, 0.f);
                        float v1 = fmaxf(SPLIT_1MS * acc1[mi][t][rr * 2 + 1] +
                                         acc2[mi][t][rr * 2 + 1] + b1, 0.f);
                        __half h0, p0, h1, p1;
                        split2(v0, h0, p0);
                        split2(v1, h1, p1);
                        uint32_t hp = (uint32_t)__half_as_ushort(h0) |
                                      ((uint32_t)__half_as_ushort(h1) << 16);
                        uint32_t pp = (uint32_t)__half_as_ushort(p0) |
                                      ((uint32_t)__half_as_ushort(p1) << 16);
                        *(uint32_t*)(Oh + (size_t)g * NP1 + cg) = hp;
                        *(uint32_t*)(Op + (size_t)g * NP1 + cg) = pp;
                    }
                }
            }
        }
    } else {
#pragma unroll
        for (int t = 0; t < 4; t++) {
            int c = wn * 32 + t * 8 + lcol;
            int cg = n0 + c;
            float b0 = s_bias[c], b1 = s_bias[c + 1];
            float s0 = 0.f, s1 = 0.f, q0 = 0.f, q1 = 0.f;
#pragma unroll
            for (int mi = 0; mi < MI; mi++) {
                int gm = m0 + wm * MT_W + mi * 16 + lrow;
                float v0 = SPLIT_1MS * acc1[mi][t][0] + acc2[mi][t][0] + b0;
                float v1 = SPLIT_1MS * acc1[mi][t][1] + acc2[mi][t][1] + b1;
                float v2 = SPLIT_1MS * acc1[mi][t][2] + acc2[mi][t][2] + b0;
                float v3 = SPLIT_1MS * acc1[mi][t][3] + acc2[mi][t][3] + b1;
                if (gm >= NN) { v0 = 0.f; v1 = 0.f; }
                if (gm + 8 >= NN) { v2 = 0.f; v3 = 0.f; }
                if (cg < HP) {
                    if (gm < NN)
                        *(__half2*)(H + (size_t)gm * HP + cg) = __floats2half2_rn(v0, v1);
                    if (gm + 8 < NN)
                        *(__half2*)(H + (size_t)(gm + 8) * HP + cg) = __floats2half2_rn(v2, v3);
                }
                s0 += v0 + v2; s1 += v1 + v3;
                q0 += v0 * v0 + v2 * v2; q1 += v1 * v1 + v3 * v3;
            }
#pragma unroll
            for (int off = 4; off < 32; off <<= 1) {
                s0 += __shfl_xor_sync(0xffffffffu, s0, off);
                s1 += __shfl_xor_sync(0xffffffffu, s1, off);
                q0 += __shfl_xor_sync(0xffffffffu, q0, off);
                q1 += __shfl_xor_sync(0xffffffffu, q1, off);
            }
            if (lane < 4) {
                if (cg < DEMB) { atomicAdd(&s_sum[c], s0); atomicAdd(&s_sq[c], q0); }
                if (cg + 1 < DEMB) { atomicAdd(&s_sum[c + 1], s1); atomicAdd(&s_sq[c + 1], q1); }
            }
        }
        __syncthreads();
        if (tid < BNT) {
            int n = n0 + tid;
            if (n < DEMB) {
                atomicAdd(&colsum[n], s_sum[tid]);
                atomicAdd(&colsq[n], s_sq[tid]);
            }
        }
    }
}

// ---------------- BN finalize (also re-zeroes stats for the next layer) ----------------
__global__ void k_bnfin(const float* __restrict__ gamma, const float* __restrict__ beta) {
    int f = threadIdx.x;
    if (f >= DEMB) return;
    const float invM = 1.0f / (float)NN;
    float mu = g_colsum[f] * invM;
    float var = g_colsq[f] * invM - mu * mu;
    float a = gamma[f] * rsqrtf(var + BN_EPS);
    g_a[f] = a;
    g_c[f] = beta[f] - mu * a;
    g_colsum[f] = 0.f;   // pre-arm next layer's GEMM2 stats accumulation
    g_colsq[f] = 0.f;
}

// ---------------- pooling (reads fp16 h) ----------------
#define POOL_TILE 32
__global__ void k_pool(const int* __restrict__ gid) {
    int f = blockIdx.y * 128 + threadIdx.x;
    if (f >= DEMB) return;
    int n0 = blockIdx.x * POOL_TILE;
    float acc = 0.f;
    int cur = gid[n0];
    for (int i = 0; i < POOL_TILE; i++) {
        int n = n0 + i;
        int g = gid[n];
        if (g != cur) {
            atomicAdd(&g_pool[cur * DEMB + f], acc);
            acc = 0.f;
            cur = g;
        }
        acc += __half2float(g_h[(size_t)n * HP + f]);
    }
    atomicAdd(&g_pool[cur * DEMB + f], acc);
}

// ---------------- final ----------------
__global__ void k_final(const float* __restrict__ wt, const float* __restrict__ bt,
                        float* __restrict__ out) {
    int g = blockIdx.x;
    int o = threadIdx.x;
    float cnt = g_cnt[g];
    float inv = 1.0f / fmaxf(cnt, 1.f);
    float acc = 0.f;
    for (int f = 0; f < DEMB; f++) {
        float pf = (g_a[f] * g_pool[g * DEMB + f] + cnt * g_c[f]) * inv;
        acc += pf * wt[f * DOUT + o];
    }
    out[g * DOUT + o] = acc + bt[o];
}

// ---------------- host launcher ----------------
#define GSMEM128 (3 * (32768 + 2 * 128 * 128) + 1024)
#define GSMEM64  (3 * (32768 + 2 * 64 * 128) + 1024)

extern "C" void kernel_launch(void* const* d_in, const int* in_sizes, int n_in,
                              void* d_out, int out_size) {
    const float* node_feats = (const float*)d_in[0];
    const float* edge_feats = (const float*)d_in[1];
    const int*   src        = (const int*)d_in[2];
    const int*   dst        = (const int*)d_in[3];
    const int*   gid        = (const int*)d_in[4];
    const float* w1_0  = (const float*)d_in[5];
    const float* b1_0  = (const float*)d_in[6];
    const float* w2_0  = (const float*)d_in[7];
    const float* b2_0  = (const float*)d_in[8];
    const float* gamma0 = (const float*)d_in[9];
    const float* beta0  = (const float*)d_in[10];
    const float* w1   = (const float*)d_in[11];
    const float* b1   = (const float*)d_in[12];
    const float* w2   = (const float*)d_in[13];
    const float* b2   = (const float*)d_in[14];
    const float* gamma = (const float*)d_in[15];
    const float* beta  = (const float*)d_in[16];
    const float* wt   = (const float*)d_in[17];
    const float* bt   = (const float*)d_in[18];
    float* out = (float*)d_out;

    static bool attr_done = false;
    if (!attr_done) {
        cudaFuncSetAttribute(k_gemm<0, 128>, cudaFuncAttributeMaxDynamicSharedMemorySize, GSMEM128);
        cudaFuncSetAttribute(k_gemm<1, 128>, cudaFuncAttributeMaxDynamicSharedMemorySize, GSMEM128);
        cudaFuncSetAttribute(k_gemm<1, 64>,  cudaFuncAttributeMaxDynamicSharedMemorySize, GSMEM64);
        attr_done = true;
    }

    __half *p_ah, *p_ap, *p_th, *p_tp, *p_w1h, *p_w1q, *p_w2h, *p_w2q, *p_h;
    float *p_b1p, *p_b2p, *p_colsum, *p_colsq;
    cudaGetSymbolAddress((void**)&p_ah, g_ah);
    cudaGetSymbolAddress((void**)&p_ap, g_ap);
    cudaGetSymbolAddress((void**)&p_th, g_th);
    cudaGetSymbolAddress((void**)&p_tp, g_tp);
    cudaGetSymbolAddress((void**)&p_w1h, g_w1h);
    cudaGetSymbolAddress((void**)&p_w1q, g_w1q);
    cudaGetSymbolAddress((void**)&p_w2h, g_w2h);
    cudaGetSymbolAddress((void**)&p_w2q, g_w2q);
    cudaGetSymbolAddress((void**)&p_h, g_h);
    cudaGetSymbolAddress((void**)&p_b1p, g_b1p);
    cudaGetSymbolAddress((void**)&p_b2p, g_b2p);
    cudaGetSymbolAddress((void**)&p_colsum, g_colsum);
    cudaGetSymbolAddress((void**)&p_colsq, g_colsq);

    // ---- preprocessing ----
    k_prepw<<<(NP1 * KP0 + 255) / 256, 256>>>(w1_0, b1_0, DIN, DHID, KP0, NP1,
                                              p_w1h, p_w1q, p_b1p);
    k_prepw<<<(NP2 * KP2 + 255) / 256, 256>>>(w2_0, b2_0, DHID, DEMB, KP2, NP2,
                                              p_w2h, p_w2q, p_b2p);
    k_zero_pre<<<(NN + 255) / 256, 256>>>();
    k_zero_pool<<<(GG * DEMB + 255) / 256, 256>>>();
    k_zero_stats<<<1, 320>>>();   // establish zeros once; k_bnfin re-zeroes thereafter
    k_edge_prep<<<(EE + 255) / 256, 256>>>(dst, edge_feats);
    k_scan1<<<SCAN_NB, 1024>>>();
    k_scan2<<<1, 128>>>();
    k_scan3<<<SCAN_NB, 1024>>>();
    k_edge_fill<<<(EE + 255) / 256, 256>>>(src, dst);
    k_counts<<<(NN + 255) / 256, 256>>>(gid);

    const int MT = (NN + BM - 1) / BM;
    dim3 grid1(NP1 / 128, MT);    // n-fast
    dim3 grid2a(2, MT);
    dim3 grid2b(1, MT);

    // ---- layer 0 ----
    k_spmm0<<<(NN * 32 + 255) / 256, 256>>>(node_feats);
    k_gemm<0, 128><<<grid1, GTHREADS, GSMEM128>>>(p_ah, p_ap, KP0, p_w1h, p_w1q, p_b1p,
                                                  KP0 / BK, 0, p_th, p_tp, nullptr, nullptr, nullptr);
    k_gemm<1, 128><<<grid2a, GTHREADS, GSMEM128>>>(p_th, p_tp, KP2, p_w2h, p_w2q, p_b2p,
                                                   KP2 / BK, 0, nullptr, nullptr, p_h, p_colsum, p_colsq);
    k_gemm<1, 64><<<grid2b, GTHREADS, GSMEM64>>>(p_th, p_tp, KP2, p_w2h, p_w2q, p_b2p,
                                                 KP2 / BK, 256, nullptr, nullptr, p_h, p_colsum, p_colsq);
    k_bnfin<<<1, 320>>>(gamma0, beta0);

    // ---- layers 1..4 ----
    for (int l = 0; l < 4; l++) {
        k_prepw<<<(NP1 * KP1 + 255) / 256, 256>>>(w1 + (size_t)l * DEMB * DHID,
                                                  b1 + (size_t)l * DHID, DEMB, DHID, KP1, NP1,
                                                  p_w1h, p_w1q, p_b1p);
        k_prepw<<<(NP2 * KP2 + 255) / 256, 256>>>(w2 + (size_t)l * DHID * DEMB,
                                                  b2 + (size_t)l * DEMB, DHID, DEMB, KP2, NP2,
                                                  p_w2h, p_w2q, p_b2p);
        k_spmm300<<<NN, 128>>>();
        k_gemm<0, 128><<<grid1, GTHREADS, GSMEM128>>>(p_ah, p_ap, KP1, p_w1h, p_w1q, p_b1p,
                                                      KP1 / BK, 0, p_th, p_tp, nullptr, nullptr, nullptr);
        k_gemm<1, 128><<<grid2a, GTHREADS, GSMEM128>>>(p_th, p_tp, KP2, p_w2h, p_w2q, p_b2p,
                                                       KP2 / BK, 0, nullptr, nullptr, p_h, p_colsum, p_colsq);
        k_gemm<1, 64><<<grid2b, GTHREADS, GSMEM64>>>(p_th, p_tp, KP2, p_w2h, p_w2q, p_b2p,
                                                     KP2 / BK, 256, nullptr, nullptr, p_h, p_colsum, p_colsq);
        k_bnfin<<<1, 320>>>(gamma + (size_t)l * DEMB, beta + (size_t)l * DEMB);
    }

    // ---- readout ----
    k_pool<<<dim3(NN / POOL_TILE, (DEMB + 127) / 128), 128>>>(gid);
    k_final<<<GG, DOUT>>>(wt, bt, out);
}